// round 14
// baseline (speedup 1.0000x reference)
#include <cuda_runtime.h>
#include <cuda_bf16.h>
#include <mma.h>
#include <cstdint>
#include <cstddef>

using namespace nvcuda;

#define N_   10000
#define E_   320000
#define HID_ 128
#define Z_   64
#define H_   4
#define EP_  (E_ + N_)

// ---------------- scratch (device globals; no allocation allowed) ----------------
__device__ float    g_h0 [N_*HID_];      // x @ gcn_w
__device__ float    g_acc[N_*HID_];      // GCN aggregation
__device__ float    g_gbuf[N_*H_*HID_];  // h1 @ gat_w   [n, h*128+d]
__device__ float    g_asrc[N_*H_];
__device__ float    g_adst[N_*H_];
__device__ unsigned g_emaxu[N_*H_];
__device__ float    g_emax[N_*H_];
__device__ float    g_den[N_*H_];        // later holds 0.25/den
__device__ float    g_ex [EP_*H_];       // self loop edge i stored at (E_+i)
__device__ float    g_agg[N_*HID_];
__device__ float    g_mu [N_*Z_];
__device__ float    g_lv [N_*Z_];
__device__ float    g_zb [N_*Z_];
__device__ float    g_deg [N_];
__device__ float    g_dinv[N_];
__device__ __nv_bfloat16 g_dh[N_*Z_];    // bf16 split of decoder output d
__device__ __nv_bfloat16 g_dl[N_*Z_];
__device__ __nv_bfloat16 g_ah[N_*HID_];  // split buffer A (ping)
__device__ __nv_bfloat16 g_al[N_*HID_];
__device__ __nv_bfloat16 g_bh[N_*HID_];  // split buffer B (pong)
__device__ __nv_bfloat16 g_bl[N_*HID_];

// ---------------- helpers ----------------
__device__ __forceinline__ unsigned fenc(float f) {
    unsigned u = __float_as_uint(f);
    return (u & 0x80000000u) ? ~u : (u | 0x80000000u);
}
__device__ __forceinline__ float fdec(unsigned x) {
    unsigned u = (x & 0x80000000u) ? (x ^ 0x80000000u) : ~x;
    return __uint_as_float(u);
}

// ---------------- init: deg=1 (self loop), emax=enc(-FLT_MAX), den=0 --------------
__global__ void k_init() {
    int i = blockIdx.x * blockDim.x + threadIdx.x;
    if (i < N_) g_deg[i] = 1.0f;
    if (i < N_*H_) { g_emaxu[i] = 0x00800000u; g_den[i] = 0.0f; }
}

__global__ void k_deg(const int* __restrict__ dst) {
    int e = blockIdx.x * blockDim.x + threadIdx.x;
    if (e < E_) atomicAdd(&g_deg[dst[e]], 1.0f);
}

__global__ void k_dinv() {
    int i = blockIdx.x * blockDim.x + threadIdx.x;
    if (i < N_) g_dinv[i] = rsqrtf(g_deg[i]);
}

// GCN self-loop contribution, direct write (no atomics)
__global__ void k_gcn_self() {
    int idx = blockIdx.x * blockDim.x + threadIdx.x;
    if (idx >= N_*32) return;
    int node = idx >> 5, lane = idx & 31;
    float c = g_dinv[node]; c = c * c;
    float4 v = ((const float4*)(g_h0 + (size_t)node*HID_))[lane];
    v.x *= c; v.y *= c; v.z *= c; v.w *= c;
    ((float4*)(g_acc + (size_t)node*HID_))[lane] = v;
}

// GCN edge scatter: warp per edge, float4 vector atomics (sm_90+)
__global__ void k_gcn_scatter(const int* __restrict__ src, const int* __restrict__ dst) {
    int gi = blockIdx.x * blockDim.x + threadIdx.x;
    int e = gi >> 5, lane = gi & 31;
    if (e >= E_) return;
    int s = src[e], t = dst[e];
    float c = g_dinv[s] * g_dinv[t];
    float4 v = ((const float4*)(g_h0 + (size_t)s*HID_))[lane];
    v.x *= c; v.y *= c; v.z *= c; v.w *= c;
    atomicAdd(((float4*)(g_acc + (size_t)t*HID_)) + lane, v);
}

// fused: out_split = dekker_bf16(relu(in + bias))   (float4 granularity)
__global__ void k_bias_relu_split(const float* __restrict__ in,
                                  const float* __restrict__ b,
                                  __nv_bfloat16* __restrict__ oh,
                                  __nv_bfloat16* __restrict__ ol,
                                  int n4, int cmask4) {
    int i = blockIdx.x * blockDim.x + threadIdx.x;
    if (i >= n4) return;
    float4 v = ((const float4*)in)[i];
    const float4 bb = ((const float4*)b)[i & cmask4];
    float f0 = fmaxf(v.x + bb.x, 0.f), f1 = fmaxf(v.y + bb.y, 0.f);
    float f2 = fmaxf(v.z + bb.z, 0.f), f3 = fmaxf(v.w + bb.w, 0.f);
    __nv_bfloat16 h0 = __float2bfloat16(f0), h1 = __float2bfloat16(f1);
    __nv_bfloat16 h2 = __float2bfloat16(f2), h3 = __float2bfloat16(f3);
    ((__nv_bfloat162*)oh)[i*2+0] = __nv_bfloat162(h0, h1);
    ((__nv_bfloat162*)oh)[i*2+1] = __nv_bfloat162(h2, h3);
    ((__nv_bfloat162*)ol)[i*2+0] =
        __nv_bfloat162(__float2bfloat16(f0 - __bfloat162float(h0)),
                       __float2bfloat16(f1 - __bfloat162float(h1)));
    ((__nv_bfloat162*)ol)[i*2+1] =
        __nv_bfloat162(__float2bfloat16(f2 - __bfloat162float(h2)),
                       __float2bfloat16(f3 - __bfloat162float(h3)));
}

// attention logits per (node, head)
__global__ void k_att(const float* __restrict__ att_s, const float* __restrict__ att_d) {
    int i = blockIdx.x * blockDim.x + threadIdx.x;
    if (i >= N_*H_) return;
    int h = i & (H_-1);
    const float4* gr  = (const float4*)(g_gbuf + (size_t)i*HID_);
    const float4* as4 = (const float4*)(att_s + h*HID_);
    const float4* ad4 = (const float4*)(att_d + h*HID_);
    float s1 = 0.f, s2 = 0.f;
    #pragma unroll 8
    for (int d = 0; d < 32; d++) {
        float4 gv = gr[d], a = as4[d], bq = ad4[d];
        s1 += gv.x*a.x + gv.y*a.y + gv.z*a.z + gv.w*a.w;
        s2 += gv.x*bq.x + gv.y*bq.y + gv.z*bq.z + gv.w*bq.w;
    }
    g_asrc[i] = s1;
    g_adst[i] = s2;
}

// pass 1: segment max of leaky_relu(a_src[s]+a_dst[t]) over dst (edges + self loops)
__global__ void k_e1(const int* __restrict__ src, const int* __restrict__ dst) {
    int idx = blockIdx.x * blockDim.x + threadIdx.x;
    if (idx >= EP_) return;
    int s, t;
    if (idx < E_) { s = src[idx]; t = dst[idx]; } else { s = t = idx - E_; }
    #pragma unroll
    for (int h = 0; h < H_; h++) {
        float ev = g_asrc[s*H_+h] + g_adst[t*H_+h];
        ev = ev > 0.f ? ev : 0.2f * ev;
        atomicMax(&g_emaxu[t*H_+h], fenc(ev));
    }
}

__global__ void k_decode_max() {
    int i = blockIdx.x * blockDim.x + threadIdx.x;
    if (i < N_*H_) g_emax[i] = fdec(g_emaxu[i]);
}

// pass 2: ex = exp(e - emax[dst]); den[dst] += ex
__global__ void k_e2(const int* __restrict__ src, const int* __restrict__ dst) {
    int idx = blockIdx.x * blockDim.x + threadIdx.x;
    if (idx >= EP_) return;
    int s, t;
    if (idx < E_) { s = src[idx]; t = dst[idx]; } else { s = t = idx - E_; }
    #pragma unroll
    for (int h = 0; h < H_; h++) {
        float ev = g_asrc[s*H_+h] + g_adst[t*H_+h];
        ev = ev > 0.f ? ev : 0.2f * ev;
        float xv = __expf(ev - g_emax[t*H_+h]);
        g_ex[(size_t)idx*H_ + h] = xv;
        atomicAdd(&g_den[t*H_+h], xv);
    }
}

// den -> 0.25/den (folds the head mean)
__global__ void k_wden() {
    int i = blockIdx.x * blockDim.x + threadIdx.x;
    if (i < N_*H_) g_den[i] = 0.25f / g_den[i];
}

// GAT self-loop contribution, direct write
__global__ void k_agg_self() {
    int idx = blockIdx.x * blockDim.x + threadIdx.x;
    if (idx >= N_*32) return;
    int node = idx >> 5, lane = idx & 31;
    float w0 = g_ex[(size_t)(E_+node)*H_+0] * g_den[node*H_+0];
    float w1 = g_ex[(size_t)(E_+node)*H_+1] * g_den[node*H_+1];
    float w2 = g_ex[(size_t)(E_+node)*H_+2] * g_den[node*H_+2];
    float w3 = g_ex[(size_t)(E_+node)*H_+3] * g_den[node*H_+3];
    const float4* gb = (const float4*)(g_gbuf + (size_t)node*H_*HID_);
    float4 v0 = gb[lane], v1 = gb[32+lane], v2 = gb[64+lane], v3 = gb[96+lane];
    float4 m;
    m.x = w0*v0.x + w1*v1.x + w2*v2.x + w3*v3.x;
    m.y = w0*v0.y + w1*v1.y + w2*v2.y + w3*v3.y;
    m.z = w0*v0.z + w1*v1.z + w2*v2.z + w3*v3.z;
    m.w = w0*v0.w + w1*v1.w + w2*v2.w + w3*v3.w;
    ((float4*)(g_agg + (size_t)node*HID_))[lane] = m;
}

// GAT edge scatter: warp per edge, fused head-weighted sum + float4 atomics
__global__ void k_gat_scatter(const int* __restrict__ src, const int* __restrict__ dst) {
    int gi = blockIdx.x * blockDim.x + threadIdx.x;
    int e = gi >> 5, lane = gi & 31;
    if (e >= E_) return;
    int s = src[e], t = dst[e];
    float w0 = g_ex[(size_t)e*H_+0] * g_den[t*H_+0];
    float w1 = g_ex[(size_t)e*H_+1] * g_den[t*H_+1];
    float w2 = g_ex[(size_t)e*H_+2] * g_den[t*H_+2];
    float w3 = g_ex[(size_t)e*H_+3] * g_den[t*H_+3];
    const float4* gb = (const float4*)(g_gbuf + (size_t)s*H_*HID_);
    float4 v0 = gb[lane], v1 = gb[32+lane], v2 = gb[64+lane], v3 = gb[96+lane];
    float4 m;
    m.x = w0*v0.x + w1*v1.x + w2*v2.x + w3*v3.x;
    m.y = w0*v0.y + w1*v1.y + w2*v2.y + w3*v3.y;
    m.z = w0*v0.z + w1*v1.z + w2*v2.z + w3*v3.z;
    m.w = w0*v0.w + w1*v1.w + w2*v2.w + w3*v3.w;
    atomicAdd(((float4*)(g_agg + (size_t)t*HID_)) + lane, m);
}

// reparameterize + copy mu/logvar to output + split z (fused)
__global__ void k_reparam(const float* __restrict__ eps,
                          float* __restrict__ omu, float* __restrict__ olv,
                          __nv_bfloat16* __restrict__ zh,
                          __nv_bfloat16* __restrict__ zl, int wr) {
    int i = blockIdx.x * blockDim.x + threadIdx.x;
    if (i >= N_*Z_) return;
    float lv = g_lv[i];
    float mu = g_mu[i];
    float lvc = fminf(10.0f, fmaxf(-10.0f, lv));
    float z = mu + eps[i] * expf(0.5f * lvc);
    g_zb[i] = z;
    __nv_bfloat16 h = __float2bfloat16(z);
    zh[i] = h;
    zl[i] = __float2bfloat16(z - __bfloat162float(h));
    if (wr) { omu[i] = mu; olv[i] = lv; }
}

// bf16 Dekker split (only used for the fp32 input x)
__global__ void k_split_arr(const float* __restrict__ in,
                            __nv_bfloat16* __restrict__ oh,
                            __nv_bfloat16* __restrict__ ol, int n4) {
    int i = blockIdx.x * blockDim.x + threadIdx.x;
    if (i >= n4) return;
    float4 v = ((const float4*)in)[i];
    __nv_bfloat16 h0 = __float2bfloat16(v.x), h1 = __float2bfloat16(v.y);
    __nv_bfloat16 h2 = __float2bfloat16(v.z), h3 = __float2bfloat16(v.w);
    ((__nv_bfloat162*)oh)[i*2+0] = __nv_bfloat162(h0, h1);
    ((__nv_bfloat162*)oh)[i*2+1] = __nv_bfloat162(h2, h3);
    ((__nv_bfloat162*)ol)[i*2+0] =
        __nv_bfloat162(__float2bfloat16(v.x - __bfloat162float(h0)),
                       __float2bfloat16(v.y - __bfloat162float(h1)));
    ((__nv_bfloat162*)ol)[i*2+1] =
        __nv_bfloat162(__float2bfloat16(v.z - __bfloat162float(h2)),
                       __float2bfloat16(v.w - __bfloat162float(h3)));
}

// ---------------- bf16 tensor-core GEMM (3-term split) ----------------------------
// C[M,Nc] = A @ B (+bias,+resid,relu). A pre-split (Ah/Al bf16 [M,K]), B fp32 split
// inline. Outputs: optional fp32 C, optional bf16 split (Oh/Ol) — fused epilogue.
// CTA tile 128x64, 256 thr = 8 warps (4x2), warp tile 32x32. One smem phase.
__global__ __launch_bounds__(256) void gemm_bf16(
    const __nv_bfloat16* __restrict__ Ah, const __nv_bfloat16* __restrict__ Al,
    const float* __restrict__ B, float* __restrict__ C,
    __nv_bfloat16* __restrict__ Oh, __nv_bfloat16* __restrict__ Ol,
    int M, int Nc, int K,
    const float* __restrict__ bias, const float* __restrict__ resid, int relu)
{
    extern __shared__ __nv_bfloat16 sm[];
    int lda = K + 8;
    __nv_bfloat16* sAh = sm;
    __nv_bfloat16* sAl = sAh + 128*lda;
    __nv_bfloat16* sBh = sAl + 128*lda;       // [k][n], LD 72
    __nv_bfloat16* sBl = sBh + K*72;

    int tid = threadIdx.x;
    int wid = tid >> 5;
    int warp_m = wid & 3, warp_n = wid >> 2;
    int rb = blockIdx.y * 128, cb = blockIdx.x * 64;

    {
        int kdiv8 = K >> 3;
        int itersA = (128 * kdiv8) / 256;       // 4 (K=64) or 8 (K=128)
        uint4 zero = make_uint4(0u, 0u, 0u, 0u);
        for (int u = 0; u < itersA; u++) {
            int f = tid + 256*u;
            int r = f / kdiv8, q = (f - r*kdiv8) * 8;
            uint4 vh = zero, vl = zero;
            if (rb + r < M) {
                vh = *(const uint4*)(Ah + (size_t)(rb + r)*K + q);
                vl = *(const uint4*)(Al + (size_t)(rb + r)*K + q);
            }
            *(uint4*)(sAh + r*lda + q) = vh;
            *(uint4*)(sAl + r*lda + q) = vl;
        }
        int itersB = K / 16;
        for (int u = 0; u < itersB; u++) {
            int f = tid + 256*u;
            int kr = f >> 4, cq = (f & 15) * 4;
            float4 w = *(const float4*)(B + (size_t)kr*Nc + cb + cq);
            __nv_bfloat16 h0 = __float2bfloat16(w.x), h1 = __float2bfloat16(w.y);
            __nv_bfloat16 h2 = __float2bfloat16(w.z), h3 = __float2bfloat16(w.w);
            ((__nv_bfloat162*)(sBh + kr*72 + cq))[0] = __nv_bfloat162(h0, h1);
            ((__nv_bfloat162*)(sBh + kr*72 + cq))[1] = __nv_bfloat162(h2, h3);
            ((__nv_bfloat162*)(sBl + kr*72 + cq))[0] =
                __nv_bfloat162(__float2bfloat16(w.x - __bfloat162float(h0)),
                               __float2bfloat16(w.y - __bfloat162float(h1)));
            ((__nv_bfloat162*)(sBl + kr*72 + cq))[1] =
                __nv_bfloat162(__float2bfloat16(w.z - __bfloat162float(h2)),
                               __float2bfloat16(w.w - __bfloat162float(h3)));
        }
    }
    __syncthreads();

    wmma::fragment<wmma::accumulator, 16, 16, 16, float> acc[2][2];
    #pragma unroll
    for (int i = 0; i < 2; i++)
        #pragma unroll
        for (int j = 0; j < 2; j++) wmma::fill_fragment(acc[i][j], 0.0f);

    for (int ks = 0; ks < K; ks += 16) {
        wmma::fragment<wmma::matrix_a, 16, 16, 16, __nv_bfloat16, wmma::row_major> ah[2], al[2];
        #pragma unroll
        for (int i = 0; i < 2; i++) {
            wmma::load_matrix_sync(ah[i], sAh + (warp_m*32 + i*16)*lda + ks, lda);
            wmma::load_matrix_sync(al[i], sAl + (warp_m*32 + i*16)*lda + ks, lda);
        }
        #pragma unroll
        for (int j = 0; j < 2; j++) {
            wmma::fragment<wmma::matrix_b, 16, 16, 16, __nv_bfloat16, wmma::row_major> bh, bl;
            wmma::load_matrix_sync(bh, sBh + ks*72 + warp_n*32 + j*16, 72);
            wmma::load_matrix_sync(bl, sBl + ks*72 + warp_n*32 + j*16, 72);
            #pragma unroll
            for (int i = 0; i < 2; i++) {
                wmma::mma_sync(acc[i][j], ah[i], bh, acc[i][j]);
                wmma::mma_sync(acc[i][j], ah[i], bl, acc[i][j]);
                wmma::mma_sync(acc[i][j], al[i], bh, acc[i][j]);
            }
        }
    }

    // ---- epilogue: stage in smem (reuse), coalesced fused stores ----
    __syncthreads();
    float* sC = (float*)sm;                     // 128 x 68 fp32
    #pragma unroll
    for (int i = 0; i < 2; i++)
        #pragma unroll
        for (int j = 0; j < 2; j++)
            wmma::store_matrix_sync(sC + (warp_m*32 + i*16)*68 + warp_n*32 + j*16,
                                    acc[i][j], 68, wmma::mem_row_major);
    __syncthreads();

    #pragma unroll
    for (int u = 0; u < 8; u++) {
        int f = tid + 256*u;                    // 0..2047 -> 128 rows x 16 float4
        int r = f >> 4, cq = (f & 15) * 4;
        int gr = rb + r;
        if (gr >= M) continue;
        float v[4];
        #pragma unroll
        for (int j = 0; j < 4; j++) {
            v[j] = sC[r*68 + cq + j];
            if (bias)  v[j] += bias[cb + cq + j];
            if (resid) v[j] += resid[(size_t)gr*Nc + cb + cq + j];
            if (relu)  v[j] = fmaxf(v[j], 0.f);
        }
        size_t off = (size_t)gr*Nc + cb + cq;
        if (C) *(float4*)(C + off) = make_float4(v[0], v[1], v[2], v[3]);
        if (Oh) {
            __nv_bfloat16 h0 = __float2bfloat16(v[0]), h1 = __float2bfloat16(v[1]);
            __nv_bfloat16 h2 = __float2bfloat16(v[2]), h3 = __float2bfloat16(v[3]);
            ((__nv_bfloat162*)(Oh + off))[0] = __nv_bfloat162(h0, h1);
            ((__nv_bfloat162*)(Oh + off))[1] = __nv_bfloat162(h2, h3);
            ((__nv_bfloat162*)(Ol + off))[0] =
                __nv_bfloat162(__float2bfloat16(v[0] - __bfloat162float(h0)),
                               __float2bfloat16(v[1] - __bfloat162float(h1)));
            ((__nv_bfloat162*)(Ol + off))[1] =
                __nv_bfloat162(__float2bfloat16(v[2] - __bfloat162float(h2)),
                               __float2bfloat16(v[3] - __bfloat162float(h3)));
        }
    }
}

// ---------------- logits SYRK (bf16 tensor cores, 3-term split) -------------------
#define SY_LD 72
__global__ __launch_bounds__(256) void syrk_bf16(const __nv_bfloat16* __restrict__ Dh,
                                                 const __nv_bfloat16* __restrict__ Dl,
                                                 float* __restrict__ C)
{
    int bx = blockIdx.x, by = blockIdx.y;
    if (by > bx) return;

    extern __shared__ __nv_bfloat16 sm[];
    __nv_bfloat16* sAh = sm;
    __nv_bfloat16* sAl = sAh + 128*SY_LD;
    __nv_bfloat16* sBh = sAl + 128*SY_LD;
    __nv_bfloat16* sBl = sBh + 128*SY_LD;

    int tid = threadIdx.x;
    int wid = tid >> 5;
    int lane = tid & 31;
    int warp_m = wid & 3, warp_n = wid >> 2;
    int rowBase = bx * 128, colBase = by * 128;

    {
        uint4 zero = make_uint4(0u, 0u, 0u, 0u);
        #pragma unroll
        for (int u = 0; u < 4; u++) {
            int f = tid + 256*u;
            int r = f >> 3, q = (f & 7) * 8;
            int ra = rowBase + r, rc = colBase + r;
            uint4 vh = zero, vl = zero, wh = zero, wl = zero;
            if (ra < N_) {
                vh = *(const uint4*)(Dh + (size_t)ra*Z_ + q);
                vl = *(const uint4*)(Dl + (size_t)ra*Z_ + q);
            }
            if (rc < N_) {
                wh = *(const uint4*)(Dh + (size_t)rc*Z_ + q);
                wl = *(const uint4*)(Dl + (size_t)rc*Z_ + q);
            }
            *(uint4*)(sAh + r*SY_LD + q) = vh;
            *(uint4*)(sAl + r*SY_LD + q) = vl;
            *(uint4*)(sBh + r*SY_LD + q) = wh;
            *(uint4*)(sBl + r*SY_LD + q) = wl;
        }
    }
    __syncthreads();

    wmma::fragment<wmma::accumulator, 16, 16, 16, float> acc[2][4];
    #pragma unroll
    for (int i = 0; i < 2; i++)
        #pragma unroll
        for (int j = 0; j < 4; j++) wmma::fill_fragment(acc[i][j], 0.0f);

    #pragma unroll
    for (int ks = 0; ks < 64; ks += 16) {
        wmma::fragment<wmma::matrix_a, 16, 16, 16, __nv_bfloat16, wmma::row_major> ah[2], al[2];
        #pragma unroll
        for (int i = 0; i < 2; i++) {
            wmma::load_matrix_sync(ah[i], sAh + (warp_m*32 + i*16)*SY_LD + ks, SY_LD);
            wmma::load_matrix_sync(al[i], sAl + (warp_m*32 + i*16)*SY_LD + ks, SY_LD);
        }
        #pragma unroll
        for (int j = 0; j < 4; j++) {
            wmma::fragment<wmma::matrix_b, 16, 16, 16, __nv_bfloat16, wmma::col_major> bh, bl;
            wmma::load_matrix_sync(bh, sBh + (warp_n*64 + j*16)*SY_LD + ks, SY_LD);
            wmma::load_matrix_sync(bl, sBl + (warp_n*64 + j*16)*SY_LD + ks, SY_LD);
            #pragma unroll
            for (int i = 0; i < 2; i++) {
                wmma::mma_sync(acc[i][j], ah[i], bh, acc[i][j]);
                wmma::mma_sync(acc[i][j], ah[i], bl, acc[i][j]);
                wmma::mma_sync(acc[i][j], al[i], bh, acc[i][j]);
            }
        }
    }

    __syncthreads();
    float* stageBase = (float*)sm;
    float* stg = stageBase + wid * (16*18);

    bool guard = (rowBase + 128 > N_);
    if (!guard) {
        #pragma unroll
        for (int i = 0; i < 2; i++)
            #pragma unroll
            for (int j = 0; j < 4; j++) {
                int R0 = rowBase + warp_m*32 + i*16;
                int C0 = colBase + warp_n*64 + j*16;
                wmma::store_matrix_sync(C + (size_t)R0*N_ + C0, acc[i][j], N_,
                                        wmma::mem_row_major);
                if (bx != by) {
                    wmma::store_matrix_sync(stg, acc[i][j], 18, wmma::mem_row_major);
                    __syncwarp();
                    #pragma unroll
                    for (int p = 0; p < 2; p++) {
                        int idx = lane + p*32;
                        int c = idx >> 2, gq = idx & 3;
                        float4 t = make_float4(stg[(gq*4+0)*18 + c],
                                               stg[(gq*4+1)*18 + c],
                                               stg[(gq*4+2)*18 + c],
                                               stg[(gq*4+3)*18 + c]);
                        *(float4*)(C + (size_t)(C0 + c)*N_ + R0 + gq*4) = t;
                    }
                    __syncwarp();
                }
            }
    } else {
        #pragma unroll
        for (int i = 0; i < 2; i++)
            #pragma unroll
            for (int j = 0; j < 4; j++) {
                wmma::store_matrix_sync(stg, acc[i][j], 18, wmma::mem_row_major);
                __syncwarp();
                int R0 = rowBase + warp_m*32 + i*16;
                int C0 = colBase + warp_n*64 + j*16;
                #pragma unroll
                for (int e = 0; e < 8; e++) {
                    int idx = lane + e*32;
                    int r = idx >> 4, c = idx & 15;
                    int R = R0 + r, Cc = C0 + c;
                    if (R < N_ && Cc < N_) {
                        float v = stg[r*18 + c];
                        C[(size_t)R*N_ + Cc] = v;
                        if (bx != by) C[(size_t)Cc*N_ + R] = v;
                    }
                }
                __syncwarp();
            }
    }
}

// ---------------- launch ----------------
static inline int cdiv(int a, int b) { return (a + b - 1) / b; }

extern "C" void kernel_launch(void* const* d_in, const int* in_sizes, int n_in,
                              void* d_out, int out_size) {
    (void)in_sizes; (void)n_in;
    const float* x     = (const float*)d_in[0];
    const int*   ei    = (const int*)  d_in[1];
    const float* eps   = (const float*)d_in[2];
    const float* gcn_w = (const float*)d_in[3];
    const float* gcn_b = (const float*)d_in[4];
    const float* gat_w = (const float*)d_in[5];
    const float* att_s = (const float*)d_in[6];
    const float* att_d = (const float*)d_in[7];
    const float* gat_b = (const float*)d_in[8];
    const float* w1    = (const float*)d_in[9];
    const float* b1    = (const float*)d_in[10];
    const float* w2    = (const float*)d_in[11];
    const float* b2    = (const float*)d_in[12];
    const float* mu_w  = (const float*)d_in[13];
    const float* mu_b  = (const float*)d_in[14];
    const float* lv_w  = (const float*)d_in[15];
    const float* lv_b  = (const float*)d_in[16];
    const float* dw1   = (const float*)d_in[17];
    const float* db1   = (const float*)d_in[18];
    const float* dw2   = (const float*)d_in[19];
    const float* db2   = (const float*)d_in[20];
    const int* srcp = ei;
    const int* dstp = ei + E_;
    float* out = (float*)d_out;

    float *ph0, *pacc, *pg, *pagg, *pmu, *plv, *pz;
    __nv_bfloat16 *pdh, *pdl, *pah, *pal, *pbh, *pbl;
    cudaGetSymbolAddress((void**)&ph0,  g_h0);
    cudaGetSymbolAddress((void**)&pacc, g_acc);
    cudaGetSymbolAddress((void**)&pg,   g_gbuf);
    cudaGetSymbolAddress((void**)&pagg, g_agg);
    cudaGetSymbolAddress((void**)&pmu,  g_mu);
    cudaGetSymbolAddress((void**)&plv,  g_lv);
    cudaGetSymbolAddress((void**)&pz,   g_zb);
    cudaGetSymbolAddress((void**)&pdh,  g_dh);
    cudaGetSymbolAddress((void**)&pdl,  g_dl);
    cudaGetSymbolAddress((void**)&pah,  g_ah);
    cudaGetSymbolAddress((void**)&pal,  g_al);
    cudaGetSymbolAddress((void**)&pbh,  g_bh);
    cudaGetSymbolAddress((void**)&pbl,  g_bl);

    const int T = 256;
    const int GM = cdiv(N_, 128);  // 79
    const int SYRK_SMEM = 4 * 128 * SY_LD * (int)sizeof(__nv_bfloat16);       // 73728
    const int GEMM_SMEM_128 = (2*128*(128+8) + 2*128*72) * (int)sizeof(__nv_bfloat16);
    const int GEMM_SMEM_64  = (2*128*(64+8)  + 2*64*72)  * (int)sizeof(__nv_bfloat16);
    static int attr_set = 0;
    if (!attr_set) {
        cudaFuncSetAttribute(syrk_bf16, cudaFuncAttributeMaxDynamicSharedMemorySize,
                             SYRK_SMEM);
        cudaFuncSetAttribute(gemm_bf16, cudaFuncAttributeMaxDynamicSharedMemorySize,
                             GEMM_SMEM_128);
        attr_set = 1;
    }

    // ---- GCN ----
    k_init<<<cdiv(N_*H_, T), T>>>();
    k_deg <<<cdiv(E_, T), T>>>(dstp);
    k_dinv<<<cdiv(N_, T), T>>>();
    k_split_arr<<<cdiv(N_*HID_/4, T), T>>>(x, pah, pal, N_*HID_/4);
    gemm_bf16<<<dim3(2, GM), 256, GEMM_SMEM_128>>>(pah, pal, gcn_w, ph0,
        nullptr, nullptr, N_, HID_, 128, nullptr, nullptr, 0);
    k_gcn_self   <<<cdiv(N_*32, T), T>>>();
    k_gcn_scatter<<<cdiv(E_*32, T), T>>>(srcp, dstp);
    // h1 = relu(acc + gcn_b) -> split directly (fp32 h1 never materialized)
    k_bias_relu_split<<<cdiv(N_*HID_/4, T), T>>>(pacc, gcn_b, pah, pal,
                                                 N_*HID_/4, 31);

    // ---- GAT ----
    gemm_bf16<<<dim3(8, GM), 256, GEMM_SMEM_128>>>(pah, pal, gat_w, pg,
        nullptr, nullptr, N_, H_*HID_, 128, nullptr, nullptr, 0);
    k_att<<<cdiv(N_*H_, T), T>>>(att_s, att_d);
    k_e1 <<<cdiv(EP_, T), T>>>(srcp, dstp);
    k_decode_max<<<cdiv(N_*H_, T), T>>>();
    k_e2 <<<cdiv(EP_, T), T>>>(srcp, dstp);
    k_wden<<<cdiv(N_*H_, T), T>>>();
    k_agg_self   <<<cdiv(N_*32, T), T>>>();
    k_gat_scatter<<<cdiv(E_*32, T), T>>>(srcp, dstp);
    // h2 = relu(agg + gat_b) -> split directly
    k_bias_relu_split<<<cdiv(N_*HID_/4, T), T>>>(pagg, gat_b, pah, pal,
                                                 N_*HID_/4, 31);

    // ---- encoder MLP (h3, h4 never materialized in fp32) ----
    gemm_bf16<<<dim3(2, GM), 256, GEMM_SMEM_128>>>(pah, pal, w1, nullptr,
        pbh, pbl, N_, HID_, 128, b1, nullptr, 1);
    gemm_bf16<<<dim3(2, GM), 256, GEMM_SMEM_128>>>(pbh, pbl, w2, nullptr,
        pah, pal, N_, HID_, 128, b2, nullptr, 1);
    gemm_bf16<<<dim3(1, GM), 256, GEMM_SMEM_128>>>(pah, pal, mu_w, pmu,
        nullptr, nullptr, N_, Z_, 128, mu_b, nullptr, 0);
    gemm_bf16<<<dim3(1, GM), 256, GEMM_SMEM_128>>>(pah, pal, lv_w, plv,
        nullptr, nullptr, N_, Z_, 128, lv_b, nullptr, 0);

    // ---- reparameterize (writes z fp32 + z split + mu/lv outputs) ----
    int wr = ((size_t)out_size >= (size_t)N_*N_ + 2u*N_*Z_) ? 1 : 0;
    k_reparam<<<cdiv(N_*Z_, T), T>>>(eps, out + (size_t)N_*N_,
                                     out + (size_t)N_*N_ + (size_t)N_*Z_,
                                     pbh, pbl, wr);

    // ---- decoder (d1 fp32 never materialized; d only as split dh/dl) ----
    gemm_bf16<<<dim3(2, GM), 256, GEMM_SMEM_64>>>(pbh, pbl, dw1, nullptr,
        pah, pal, N_, HID_, 64, db1, nullptr, 1);
    gemm_bf16<<<dim3(1, GM), 256, GEMM_SMEM_128>>>(pah, pal, dw2, nullptr,
        pdh, pdl, N_, Z_, 128, db2, pz, 0);

    // ---- logits = d @ d^T (symmetric, bf16 tensor cores) ----
    syrk_bf16<<<dim3(cdiv(N_, 128), cdiv(N_, 128)), 256, SYRK_SMEM>>>(pdh, pdl, out);
}

// round 15
// speedup vs baseline: 1.0091x; 1.0091x over previous
#include <cuda_runtime.h>
#include <cuda_bf16.h>
#include <mma.h>
#include <cstdint>
#include <cstddef>

using namespace nvcuda;

#define N_   10000
#define E_   320000
#define HID_ 128
#define Z_   64
#define H_   4
#define EP_  (E_ + N_)

// ---------------- scratch (device globals; no allocation allowed) ----------------
__device__ float    g_h0 [N_*HID_];      // x @ gcn_w
__device__ float    g_acc[N_*HID_];      // GCN aggregation
__device__ float    g_gbuf[N_*H_*HID_];  // h1 @ gat_w   [n, h*128+d]
__device__ float    g_asrc[N_*H_];
__device__ float    g_adst[N_*H_];
__device__ unsigned g_emaxu[N_*H_];
__device__ float    g_emax[N_*H_];
__device__ float    g_den[N_*H_];        // later holds 0.25/den
__device__ float    g_ex [EP_*H_];       // self loop edge i stored at (E_+i)
__device__ float    g_agg[N_*HID_];
__device__ float    g_mu [N_*Z_];
__device__ float    g_lv [N_*Z_];
__device__ float    g_zb [N_*Z_];
__device__ float    g_deg [N_];
__device__ float    g_dinv[N_];
__device__ __nv_bfloat16 g_dh[N_*Z_];    // bf16 split of decoder output d
__device__ __nv_bfloat16 g_dl[N_*Z_];
__device__ __nv_bfloat16 g_ah[N_*HID_];  // split buffer A (ping)
__device__ __nv_bfloat16 g_al[N_*HID_];
__device__ __nv_bfloat16 g_bh[N_*HID_];  // split buffer B (pong)
__device__ __nv_bfloat16 g_bl[N_*HID_];

// ---------------- helpers ----------------
__device__ __forceinline__ unsigned fenc(float f) {
    unsigned u = __float_as_uint(f);
    return (u & 0x80000000u) ? ~u : (u | 0x80000000u);
}
__device__ __forceinline__ float fdec(unsigned x) {
    unsigned u = (x & 0x80000000u) ? (x ^ 0x80000000u) : ~x;
    return __uint_as_float(u);
}

// ---------------- init: deg=1 (self loop), emax=enc(-FLT_MAX), den=0 --------------
__global__ void k_init() {
    int i = blockIdx.x * blockDim.x + threadIdx.x;
    if (i < N_) g_deg[i] = 1.0f;
    if (i < N_*H_) { g_emaxu[i] = 0x00800000u; g_den[i] = 0.0f; }
}

__global__ void k_deg(const int* __restrict__ dst) {
    int e = blockIdx.x * blockDim.x + threadIdx.x;
    if (e < E_) atomicAdd(&g_deg[dst[e]], 1.0f);
}

__global__ void k_dinv() {
    int i = blockIdx.x * blockDim.x + threadIdx.x;
    if (i < N_) g_dinv[i] = rsqrtf(g_deg[i]);
}

// GCN self-loop contribution, direct write (no atomics)
__global__ void k_gcn_self() {
    int idx = blockIdx.x * blockDim.x + threadIdx.x;
    if (idx >= N_*32) return;
    int node = idx >> 5, lane = idx & 31;
    float c = g_dinv[node]; c = c * c;
    float4 v = ((const float4*)(g_h0 + (size_t)node*HID_))[lane];
    v.x *= c; v.y *= c; v.z *= c; v.w *= c;
    ((float4*)(g_acc + (size_t)node*HID_))[lane] = v;
}

// GCN edge scatter: warp per edge, float4 vector atomics (sm_90+)
__global__ void k_gcn_scatter(const int* __restrict__ src, const int* __restrict__ dst) {
    int gi = blockIdx.x * blockDim.x + threadIdx.x;
    int e = gi >> 5, lane = gi & 31;
    if (e >= E_) return;
    int s = src[e], t = dst[e];
    float c = g_dinv[s] * g_dinv[t];
    float4 v = ((const float4*)(g_h0 + (size_t)s*HID_))[lane];
    v.x *= c; v.y *= c; v.z *= c; v.w *= c;
    atomicAdd(((float4*)(g_acc + (size_t)t*HID_)) + lane, v);
}

// fused: out_split = dekker_bf16(relu(in + bias))   (float4 granularity)
__global__ void k_bias_relu_split(const float* __restrict__ in,
                                  const float* __restrict__ b,
                                  __nv_bfloat16* __restrict__ oh,
                                  __nv_bfloat16* __restrict__ ol,
                                  int n4, int cmask4) {
    int i = blockIdx.x * blockDim.x + threadIdx.x;
    if (i >= n4) return;
    float4 v = ((const float4*)in)[i];
    const float4 bb = ((const float4*)b)[i & cmask4];
    float f0 = fmaxf(v.x + bb.x, 0.f), f1 = fmaxf(v.y + bb.y, 0.f);
    float f2 = fmaxf(v.z + bb.z, 0.f), f3 = fmaxf(v.w + bb.w, 0.f);
    __nv_bfloat16 h0 = __float2bfloat16(f0), h1 = __float2bfloat16(f1);
    __nv_bfloat16 h2 = __float2bfloat16(f2), h3 = __float2bfloat16(f3);
    ((__nv_bfloat162*)oh)[i*2+0] = __nv_bfloat162(h0, h1);
    ((__nv_bfloat162*)oh)[i*2+1] = __nv_bfloat162(h2, h3);
    ((__nv_bfloat162*)ol)[i*2+0] =
        __nv_bfloat162(__float2bfloat16(f0 - __bfloat162float(h0)),
                       __float2bfloat16(f1 - __bfloat162float(h1)));
    ((__nv_bfloat162*)ol)[i*2+1] =
        __nv_bfloat162(__float2bfloat16(f2 - __bfloat162float(h2)),
                       __float2bfloat16(f3 - __bfloat162float(h3)));
}

// attention logits per (node, head)
__global__ void k_att(const float* __restrict__ att_s, const float* __restrict__ att_d) {
    int i = blockIdx.x * blockDim.x + threadIdx.x;
    if (i >= N_*H_) return;
    int h = i & (H_-1);
    const float4* gr  = (const float4*)(g_gbuf + (size_t)i*HID_);
    const float4* as4 = (const float4*)(att_s + h*HID_);
    const float4* ad4 = (const float4*)(att_d + h*HID_);
    float s1 = 0.f, s2 = 0.f;
    #pragma unroll 8
    for (int d = 0; d < 32; d++) {
        float4 gv = gr[d], a = as4[d], bq = ad4[d];
        s1 += gv.x*a.x + gv.y*a.y + gv.z*a.z + gv.w*a.w;
        s2 += gv.x*bq.x + gv.y*bq.y + gv.z*bq.z + gv.w*bq.w;
    }
    g_asrc[i] = s1;
    g_adst[i] = s2;
}

// pass 1: segment max of leaky_relu(a_src[s]+a_dst[t]) over dst (edges + self loops)
__global__ void k_e1(const int* __restrict__ src, const int* __restrict__ dst) {
    int idx = blockIdx.x * blockDim.x + threadIdx.x;
    if (idx >= EP_) return;
    int s, t;
    if (idx < E_) { s = src[idx]; t = dst[idx]; } else { s = t = idx - E_; }
    #pragma unroll
    for (int h = 0; h < H_; h++) {
        float ev = g_asrc[s*H_+h] + g_adst[t*H_+h];
        ev = ev > 0.f ? ev : 0.2f * ev;
        atomicMax(&g_emaxu[t*H_+h], fenc(ev));
    }
}

__global__ void k_decode_max() {
    int i = blockIdx.x * blockDim.x + threadIdx.x;
    if (i < N_*H_) g_emax[i] = fdec(g_emaxu[i]);
}

// pass 2: ex = exp(e - emax[dst]); den[dst] += ex
__global__ void k_e2(const int* __restrict__ src, const int* __restrict__ dst) {
    int idx = blockIdx.x * blockDim.x + threadIdx.x;
    if (idx >= EP_) return;
    int s, t;
    if (idx < E_) { s = src[idx]; t = dst[idx]; } else { s = t = idx - E_; }
    #pragma unroll
    for (int h = 0; h < H_; h++) {
        float ev = g_asrc[s*H_+h] + g_adst[t*H_+h];
        ev = ev > 0.f ? ev : 0.2f * ev;
        float xv = __expf(ev - g_emax[t*H_+h]);
        g_ex[(size_t)idx*H_ + h] = xv;
        atomicAdd(&g_den[t*H_+h], xv);
    }
}

// den -> 0.25/den (folds the head mean)
__global__ void k_wden() {
    int i = blockIdx.x * blockDim.x + threadIdx.x;
    if (i < N_*H_) g_den[i] = 0.25f / g_den[i];
}

// GAT self-loop contribution, direct write
__global__ void k_agg_self() {
    int idx = blockIdx.x * blockDim.x + threadIdx.x;
    if (idx >= N_*32) return;
    int node = idx >> 5, lane = idx & 31;
    float w0 = g_ex[(size_t)(E_+node)*H_+0] * g_den[node*H_+0];
    float w1 = g_ex[(size_t)(E_+node)*H_+1] * g_den[node*H_+1];
    float w2 = g_ex[(size_t)(E_+node)*H_+2] * g_den[node*H_+2];
    float w3 = g_ex[(size_t)(E_+node)*H_+3] * g_den[node*H_+3];
    const float4* gb = (const float4*)(g_gbuf + (size_t)node*H_*HID_);
    float4 v0 = gb[lane], v1 = gb[32+lane], v2 = gb[64+lane], v3 = gb[96+lane];
    float4 m;
    m.x = w0*v0.x + w1*v1.x + w2*v2.x + w3*v3.x;
    m.y = w0*v0.y + w1*v1.y + w2*v2.y + w3*v3.y;
    m.z = w0*v0.z + w1*v1.z + w2*v2.z + w3*v3.z;
    m.w = w0*v0.w + w1*v1.w + w2*v2.w + w3*v3.w;
    ((float4*)(g_agg + (size_t)node*HID_))[lane] = m;
}

// GAT edge scatter: warp per edge, fused head-weighted sum + float4 atomics
__global__ void k_gat_scatter(const int* __restrict__ src, const int* __restrict__ dst) {
    int gi = blockIdx.x * blockDim.x + threadIdx.x;
    int e = gi >> 5, lane = gi & 31;
    if (e >= E_) return;
    int s = src[e], t = dst[e];
    float w0 = g_ex[(size_t)e*H_+0] * g_den[t*H_+0];
    float w1 = g_ex[(size_t)e*H_+1] * g_den[t*H_+1];
    float w2 = g_ex[(size_t)e*H_+2] * g_den[t*H_+2];
    float w3 = g_ex[(size_t)e*H_+3] * g_den[t*H_+3];
    const float4* gb = (const float4*)(g_gbuf + (size_t)s*H_*HID_);
    float4 v0 = gb[lane], v1 = gb[32+lane], v2 = gb[64+lane], v3 = gb[96+lane];
    float4 m;
    m.x = w0*v0.x + w1*v1.x + w2*v2.x + w3*v3.x;
    m.y = w0*v0.y + w1*v1.y + w2*v2.y + w3*v3.y;
    m.z = w0*v0.z + w1*v1.z + w2*v2.z + w3*v3.z;
    m.w = w0*v0.w + w1*v1.w + w2*v2.w + w3*v3.w;
    atomicAdd(((float4*)(g_agg + (size_t)t*HID_)) + lane, m);
}

// reparameterize + copy mu/logvar to output + split z (fused)
__global__ void k_reparam(const float* __restrict__ eps,
                          float* __restrict__ omu, float* __restrict__ olv,
                          __nv_bfloat16* __restrict__ zh,
                          __nv_bfloat16* __restrict__ zl, int wr) {
    int i = blockIdx.x * blockDim.x + threadIdx.x;
    if (i >= N_*Z_) return;
    float lv = g_lv[i];
    float mu = g_mu[i];
    float lvc = fminf(10.0f, fmaxf(-10.0f, lv));
    float z = mu + eps[i] * expf(0.5f * lvc);
    g_zb[i] = z;
    __nv_bfloat16 h = __float2bfloat16(z);
    zh[i] = h;
    zl[i] = __float2bfloat16(z - __bfloat162float(h));
    if (wr) { omu[i] = mu; olv[i] = lv; }
}

// bf16 Dekker split (only used for the fp32 input x)
__global__ void k_split_arr(const float* __restrict__ in,
                            __nv_bfloat16* __restrict__ oh,
                            __nv_bfloat16* __restrict__ ol, int n4) {
    int i = blockIdx.x * blockDim.x + threadIdx.x;
    if (i >= n4) return;
    float4 v = ((const float4*)in)[i];
    __nv_bfloat16 h0 = __float2bfloat16(v.x), h1 = __float2bfloat16(v.y);
    __nv_bfloat16 h2 = __float2bfloat16(v.z), h3 = __float2bfloat16(v.w);
    ((__nv_bfloat162*)oh)[i*2+0] = __nv_bfloat162(h0, h1);
    ((__nv_bfloat162*)oh)[i*2+1] = __nv_bfloat162(h2, h3);
    ((__nv_bfloat162*)ol)[i*2+0] =
        __nv_bfloat162(__float2bfloat16(v.x - __bfloat162float(h0)),
                       __float2bfloat16(v.y - __bfloat162float(h1)));
    ((__nv_bfloat162*)ol)[i*2+1] =
        __nv_bfloat162(__float2bfloat16(v.z - __bfloat162float(h2)),
                       __float2bfloat16(v.w - __bfloat162float(h3)));
}

// ---------------- bf16 tensor-core GEMM (3-term split) ----------------------------
// C[M,Nc] = A @ B (+bias,+resid,relu). A pre-split (Ah/Al bf16 [M,K]), B fp32 split
// inline. Outputs: optional fp32 C, optional bf16 split (Oh/Ol) — fused epilogue.
// CTA tile 128x64, 256 thr = 8 warps (4x2), warp tile 32x32. One smem phase.
__global__ __launch_bounds__(256) void gemm_bf16(
    const __nv_bfloat16* __restrict__ Ah, const __nv_bfloat16* __restrict__ Al,
    const float* __restrict__ B, float* __restrict__ C,
    __nv_bfloat16* __restrict__ Oh, __nv_bfloat16* __restrict__ Ol,
    int M, int Nc, int K,
    const float* __restrict__ bias, const float* __restrict__ resid, int relu)
{
    extern __shared__ __nv_bfloat16 sm[];
    int lda = K + 8;
    __nv_bfloat16* sAh = sm;
    __nv_bfloat16* sAl = sAh + 128*lda;
    __nv_bfloat16* sBh = sAl + 128*lda;       // [k][n], LD 72
    __nv_bfloat16* sBl = sBh + K*72;

    int tid = threadIdx.x;
    int wid = tid >> 5;
    int warp_m = wid & 3, warp_n = wid >> 2;
    int rb = blockIdx.y * 128, cb = blockIdx.x * 64;

    {
        int kdiv8 = K >> 3;
        int itersA = (128 * kdiv8) / 256;       // 4 (K=64) or 8 (K=128)
        uint4 zero = make_uint4(0u, 0u, 0u, 0u);
        for (int u = 0; u < itersA; u++) {
            int f = tid + 256*u;
            int r = f / kdiv8, q = (f - r*kdiv8) * 8;
            uint4 vh = zero, vl = zero;
            if (rb + r < M) {
                vh = *(const uint4*)(Ah + (size_t)(rb + r)*K + q);
                vl = *(const uint4*)(Al + (size_t)(rb + r)*K + q);
            }
            *(uint4*)(sAh + r*lda + q) = vh;
            *(uint4*)(sAl + r*lda + q) = vl;
        }
        int itersB = K / 16;
        for (int u = 0; u < itersB; u++) {
            int f = tid + 256*u;
            int kr = f >> 4, cq = (f & 15) * 4;
            float4 w = *(const float4*)(B + (size_t)kr*Nc + cb + cq);
            __nv_bfloat16 h0 = __float2bfloat16(w.x), h1 = __float2bfloat16(w.y);
            __nv_bfloat16 h2 = __float2bfloat16(w.z), h3 = __float2bfloat16(w.w);
            ((__nv_bfloat162*)(sBh + kr*72 + cq))[0] = __nv_bfloat162(h0, h1);
            ((__nv_bfloat162*)(sBh + kr*72 + cq))[1] = __nv_bfloat162(h2, h3);
            ((__nv_bfloat162*)(sBl + kr*72 + cq))[0] =
                __nv_bfloat162(__float2bfloat16(w.x - __bfloat162float(h0)),
                               __float2bfloat16(w.y - __bfloat162float(h1)));
            ((__nv_bfloat162*)(sBl + kr*72 + cq))[1] =
                __nv_bfloat162(__float2bfloat16(w.z - __bfloat162float(h2)),
                               __float2bfloat16(w.w - __bfloat162float(h3)));
        }
    }
    __syncthreads();

    wmma::fragment<wmma::accumulator, 16, 16, 16, float> acc[2][2];
    #pragma unroll
    for (int i = 0; i < 2; i++)
        #pragma unroll
        for (int j = 0; j < 2; j++) wmma::fill_fragment(acc[i][j], 0.0f);

    for (int ks = 0; ks < K; ks += 16) {
        wmma::fragment<wmma::matrix_a, 16, 16, 16, __nv_bfloat16, wmma::row_major> ah[2], al[2];
        #pragma unroll
        for (int i = 0; i < 2; i++) {
            wmma::load_matrix_sync(ah[i], sAh + (warp_m*32 + i*16)*lda + ks, lda);
            wmma::load_matrix_sync(al[i], sAl + (warp_m*32 + i*16)*lda + ks, lda);
        }
        #pragma unroll
        for (int j = 0; j < 2; j++) {
            wmma::fragment<wmma::matrix_b, 16, 16, 16, __nv_bfloat16, wmma::row_major> bh, bl;
            wmma::load_matrix_sync(bh, sBh + ks*72 + warp_n*32 + j*16, 72);
            wmma::load_matrix_sync(bl, sBl + ks*72 + warp_n*32 + j*16, 72);
            #pragma unroll
            for (int i = 0; i < 2; i++) {
                wmma::mma_sync(acc[i][j], ah[i], bh, acc[i][j]);
                wmma::mma_sync(acc[i][j], ah[i], bl, acc[i][j]);
                wmma::mma_sync(acc[i][j], al[i], bh, acc[i][j]);
            }
        }
    }

    // ---- epilogue: stage in smem (reuse), coalesced fused stores ----
    __syncthreads();
    float* sC = (float*)sm;                     // 128 x 68 fp32
    #pragma unroll
    for (int i = 0; i < 2; i++)
        #pragma unroll
        for (int j = 0; j < 2; j++)
            wmma::store_matrix_sync(sC + (warp_m*32 + i*16)*68 + warp_n*32 + j*16,
                                    acc[i][j], 68, wmma::mem_row_major);
    __syncthreads();

    #pragma unroll
    for (int u = 0; u < 8; u++) {
        int f = tid + 256*u;                    // 0..2047 -> 128 rows x 16 float4
        int r = f >> 4, cq = (f & 15) * 4;
        int gr = rb + r;
        if (gr >= M) continue;
        float v[4];
        #pragma unroll
        for (int j = 0; j < 4; j++) {
            v[j] = sC[r*68 + cq + j];
            if (bias)  v[j] += bias[cb + cq + j];
            if (resid) v[j] += resid[(size_t)gr*Nc + cb + cq + j];
            if (relu)  v[j] = fmaxf(v[j], 0.f);
        }
        size_t off = (size_t)gr*Nc + cb + cq;
        if (C) *(float4*)(C + off) = make_float4(v[0], v[1], v[2], v[3]);
        if (Oh) {
            __nv_bfloat16 h0 = __float2bfloat16(v[0]), h1 = __float2bfloat16(v[1]);
            __nv_bfloat16 h2 = __float2bfloat16(v[2]), h3 = __float2bfloat16(v[3]);
            ((__nv_bfloat162*)(Oh + off))[0] = __nv_bfloat162(h0, h1);
            ((__nv_bfloat162*)(Oh + off))[1] = __nv_bfloat162(h2, h3);
            ((__nv_bfloat162*)(Ol + off))[0] =
                __nv_bfloat162(__float2bfloat16(v[0] - __bfloat162float(h0)),
                               __float2bfloat16(v[1] - __bfloat162float(h1)));
            ((__nv_bfloat162*)(Ol + off))[1] =
                __nv_bfloat162(__float2bfloat16(v[2] - __bfloat162float(h2)),
                               __float2bfloat16(v[3] - __bfloat162float(h3)));
        }
    }
}

// ---------------- logits SYRK (bf16 tensor cores, 3-term split) -------------------
#define SY_LD 72
__global__ __launch_bounds__(256) void syrk_bf16(const __nv_bfloat16* __restrict__ Dh,
                                                 const __nv_bfloat16* __restrict__ Dl,
                                                 float* __restrict__ C)
{
    int bx = blockIdx.x, by = blockIdx.y;
    if (by > bx) return;

    extern __shared__ __nv_bfloat16 sm[];
    __nv_bfloat16* sAh = sm;
    __nv_bfloat16* sAl = sAh + 128*SY_LD;
    __nv_bfloat16* sBh = sAl + 128*SY_LD;
    __nv_bfloat16* sBl = sBh + 128*SY_LD;

    int tid = threadIdx.x;
    int wid = tid >> 5;
    int lane = tid & 31;
    int warp_m = wid & 3, warp_n = wid >> 2;
    int rowBase = bx * 128, colBase = by * 128;

    {
        uint4 zero = make_uint4(0u, 0u, 0u, 0u);
        #pragma unroll
        for (int u = 0; u < 4; u++) {
            int f = tid + 256*u;
            int r = f >> 3, q = (f & 7) * 8;
            int ra = rowBase + r, rc = colBase + r;
            uint4 vh = zero, vl = zero, wh = zero, wl = zero;
            if (ra < N_) {
                vh = *(const uint4*)(Dh + (size_t)ra*Z_ + q);
                vl = *(const uint4*)(Dl + (size_t)ra*Z_ + q);
            }
            if (rc < N_) {
                wh = *(const uint4*)(Dh + (size_t)rc*Z_ + q);
                wl = *(const uint4*)(Dl + (size_t)rc*Z_ + q);
            }
            *(uint4*)(sAh + r*SY_LD + q) = vh;
            *(uint4*)(sAl + r*SY_LD + q) = vl;
            *(uint4*)(sBh + r*SY_LD + q) = wh;
            *(uint4*)(sBl + r*SY_LD + q) = wl;
        }
    }
    __syncthreads();

    wmma::fragment<wmma::accumulator, 16, 16, 16, float> acc[2][4];
    #pragma unroll
    for (int i = 0; i < 2; i++)
        #pragma unroll
        for (int j = 0; j < 4; j++) wmma::fill_fragment(acc[i][j], 0.0f);

    #pragma unroll
    for (int ks = 0; ks < 64; ks += 16) {
        wmma::fragment<wmma::matrix_a, 16, 16, 16, __nv_bfloat16, wmma::row_major> ah[2], al[2];
        #pragma unroll
        for (int i = 0; i < 2; i++) {
            wmma::load_matrix_sync(ah[i], sAh + (warp_m*32 + i*16)*SY_LD + ks, SY_LD);
            wmma::load_matrix_sync(al[i], sAl + (warp_m*32 + i*16)*SY_LD + ks, SY_LD);
        }
        #pragma unroll
        for (int j = 0; j < 4; j++) {
            wmma::fragment<wmma::matrix_b, 16, 16, 16, __nv_bfloat16, wmma::col_major> bh, bl;
            wmma::load_matrix_sync(bh, sBh + (warp_n*64 + j*16)*SY_LD + ks, SY_LD);
            wmma::load_matrix_sync(bl, sBl + (warp_n*64 + j*16)*SY_LD + ks, SY_LD);
            #pragma unroll
            for (int i = 0; i < 2; i++) {
                wmma::mma_sync(acc[i][j], ah[i], bh, acc[i][j]);
                wmma::mma_sync(acc[i][j], ah[i], bl, acc[i][j]);
                wmma::mma_sync(acc[i][j], al[i], bh, acc[i][j]);
            }
        }
    }

    __syncthreads();
    float* stageBase = (float*)sm;
    float* stg = stageBase + wid * (16*18);

    bool guard = (rowBase + 128 > N_);
    if (!guard) {
        #pragma unroll
        for (int i = 0; i < 2; i++)
            #pragma unroll
            for (int j = 0; j < 4; j++) {
                int R0 = rowBase + warp_m*32 + i*16;
                int C0 = colBase + warp_n*64 + j*16;
                wmma::store_matrix_sync(C + (size_t)R0*N_ + C0, acc[i][j], N_,
                                        wmma::mem_row_major);
                if (bx != by) {
                    wmma::store_matrix_sync(stg, acc[i][j], 18, wmma::mem_row_major);
                    __syncwarp();
                    #pragma unroll
                    for (int p = 0; p < 2; p++) {
                        int idx = lane + p*32;
                        int c = idx >> 2, gq = idx & 3;
                        float4 t = make_float4(stg[(gq*4+0)*18 + c],
                                               stg[(gq*4+1)*18 + c],
                                               stg[(gq*4+2)*18 + c],
                                               stg[(gq*4+3)*18 + c]);
                        *(float4*)(C + (size_t)(C0 + c)*N_ + R0 + gq*4) = t;
                    }
                    __syncwarp();
                }
            }
    } else {
        #pragma unroll
        for (int i = 0; i < 2; i++)
            #pragma unroll
            for (int j = 0; j < 4; j++) {
                wmma::store_matrix_sync(stg, acc[i][j], 18, wmma::mem_row_major);
                __syncwarp();
                int R0 = rowBase + warp_m*32 + i*16;
                int C0 = colBase + warp_n*64 + j*16;
                #pragma unroll
                for (int e = 0; e < 8; e++) {
                    int idx = lane + e*32;
                    int r = idx >> 4, c = idx & 15;
                    int R = R0 + r, Cc = C0 + c;
                    if (R < N_ && Cc < N_) {
                        float v = stg[r*18 + c];
                        C[(size_t)R*N_ + Cc] = v;
                        if (bx != by) C[(size_t)Cc*N_ + R] = v;
                    }
                }
                __syncwarp();
            }
    }
}

// ---------------- launch ----------------
static inline int cdiv(int a, int b) { return (a + b - 1) / b; }

extern "C" void kernel_launch(void* const* d_in, const int* in_sizes, int n_in,
                              void* d_out, int out_size) {
    (void)in_sizes; (void)n_in;
    const float* x     = (const float*)d_in[0];
    const int*   ei    = (const int*)  d_in[1];
    const float* eps   = (const float*)d_in[2];
    const float* gcn_w = (const float*)d_in[3];
    const float* gcn_b = (const float*)d_in[4];
    const float* gat_w = (const float*)d_in[5];
    const float* att_s = (const float*)d_in[6];
    const float* att_d = (const float*)d_in[7];
    const float* gat_b = (const float*)d_in[8];
    const float* w1    = (const float*)d_in[9];
    const float* b1    = (const float*)d_in[10];
    const float* w2    = (const float*)d_in[11];
    const float* b2    = (const float*)d_in[12];
    const float* mu_w  = (const float*)d_in[13];
    const float* mu_b  = (const float*)d_in[14];
    const float* lv_w  = (const float*)d_in[15];
    const float* lv_b  = (const float*)d_in[16];
    const float* dw1   = (const float*)d_in[17];
    const float* db1   = (const float*)d_in[18];
    const float* dw2   = (const float*)d_in[19];
    const float* db2   = (const float*)d_in[20];
    const int* srcp = ei;
    const int* dstp = ei + E_;
    float* out = (float*)d_out;

    float *ph0, *pacc, *pg, *pagg, *pmu, *plv, *pz;
    __nv_bfloat16 *pdh, *pdl, *pah, *pal, *pbh, *pbl;
    cudaGetSymbolAddress((void**)&ph0,  g_h0);
    cudaGetSymbolAddress((void**)&pacc, g_acc);
    cudaGetSymbolAddress((void**)&pg,   g_gbuf);
    cudaGetSymbolAddress((void**)&pagg, g_agg);
    cudaGetSymbolAddress((void**)&pmu,  g_mu);
    cudaGetSymbolAddress((void**)&plv,  g_lv);
    cudaGetSymbolAddress((void**)&pz,   g_zb);
    cudaGetSymbolAddress((void**)&pdh,  g_dh);
    cudaGetSymbolAddress((void**)&pdl,  g_dl);
    cudaGetSymbolAddress((void**)&pah,  g_ah);
    cudaGetSymbolAddress((void**)&pal,  g_al);
    cudaGetSymbolAddress((void**)&pbh,  g_bh);
    cudaGetSymbolAddress((void**)&pbl,  g_bl);

    const int T = 256;
    const int GM = cdiv(N_, 128);  // 79
    const int SYRK_SMEM = 4 * 128 * SY_LD * (int)sizeof(__nv_bfloat16);       // 73728
    const int GEMM_SMEM_128 = (2*128*(128+8) + 2*128*72) * (int)sizeof(__nv_bfloat16);
    const int GEMM_SMEM_64  = (2*128*(64+8)  + 2*64*72)  * (int)sizeof(__nv_bfloat16);
    static int attr_set = 0;
    if (!attr_set) {
        cudaFuncSetAttribute(syrk_bf16, cudaFuncAttributeMaxDynamicSharedMemorySize,
                             SYRK_SMEM);
        cudaFuncSetAttribute(gemm_bf16, cudaFuncAttributeMaxDynamicSharedMemorySize,
                             GEMM_SMEM_128);
        attr_set = 1;
    }

    // ---- GCN ----
    k_init<<<cdiv(N_*H_, T), T>>>();
    k_deg <<<cdiv(E_, T), T>>>(dstp);
    k_dinv<<<cdiv(N_, T), T>>>();
    k_split_arr<<<cdiv(N_*HID_/4, T), T>>>(x, pah, pal, N_*HID_/4);
    gemm_bf16<<<dim3(2, GM), 256, GEMM_SMEM_128>>>(pah, pal, gcn_w, ph0,
        nullptr, nullptr, N_, HID_, 128, nullptr, nullptr, 0);
    k_gcn_self   <<<cdiv(N_*32, T), T>>>();
    k_gcn_scatter<<<cdiv(E_*32, T), T>>>(srcp, dstp);
    // h1 = relu(acc + gcn_b) -> split directly (fp32 h1 never materialized)
    k_bias_relu_split<<<cdiv(N_*HID_/4, T), T>>>(pacc, gcn_b, pah, pal,
                                                 N_*HID_/4, 31);

    // ---- GAT ----
    gemm_bf16<<<dim3(8, GM), 256, GEMM_SMEM_128>>>(pah, pal, gat_w, pg,
        nullptr, nullptr, N_, H_*HID_, 128, nullptr, nullptr, 0);
    k_att<<<cdiv(N_*H_, T), T>>>(att_s, att_d);
    k_e1 <<<cdiv(EP_, T), T>>>(srcp, dstp);
    k_decode_max<<<cdiv(N_*H_, T), T>>>();
    k_e2 <<<cdiv(EP_, T), T>>>(srcp, dstp);
    k_wden<<<cdiv(N_*H_, T), T>>>();
    k_agg_self   <<<cdiv(N_*32, T), T>>>();
    k_gat_scatter<<<cdiv(E_*32, T), T>>>(srcp, dstp);
    // h2 = relu(agg + gat_b) -> split directly
    k_bias_relu_split<<<cdiv(N_*HID_/4, T), T>>>(pagg, gat_b, pah, pal,
                                                 N_*HID_/4, 31);

    // ---- encoder MLP (h3, h4 never materialized in fp32) ----
    gemm_bf16<<<dim3(2, GM), 256, GEMM_SMEM_128>>>(pah, pal, w1, nullptr,
        pbh, pbl, N_, HID_, 128, b1, nullptr, 1);
    gemm_bf16<<<dim3(2, GM), 256, GEMM_SMEM_128>>>(pbh, pbl, w2, nullptr,
        pah, pal, N_, HID_, 128, b2, nullptr, 1);
    gemm_bf16<<<dim3(1, GM), 256, GEMM_SMEM_128>>>(pah, pal, mu_w, pmu,
        nullptr, nullptr, N_, Z_, 128, mu_b, nullptr, 0);
    gemm_bf16<<<dim3(1, GM), 256, GEMM_SMEM_128>>>(pah, pal, lv_w, plv,
        nullptr, nullptr, N_, Z_, 128, lv_b, nullptr, 0);

    // ---- reparameterize (writes z fp32 + z split + mu/lv outputs) ----
    int wr = ((size_t)out_size >= (size_t)N_*N_ + 2u*N_*Z_) ? 1 : 0;
    k_reparam<<<cdiv(N_*Z_, T), T>>>(eps, out + (size_t)N_*N_,
                                     out + (size_t)N_*N_ + (size_t)N_*Z_,
                                     pbh, pbl, wr);

    // ---- decoder (d1 fp32 never materialized; d only as split dh/dl) ----
    gemm_bf16<<<dim3(2, GM), 256, GEMM_SMEM_64>>>(pbh, pbl, dw1, nullptr,
        pah, pal, N_, HID_, 64, db1, nullptr, 1);
    gemm_bf16<<<dim3(1, GM), 256, GEMM_SMEM_128>>>(pah, pal, dw2, nullptr,
        pdh, pdl, N_, Z_, 128, db2, pz, 0);

    // ---- logits = d @ d^T (symmetric, bf16 tensor cores) ----
    syrk_bf16<<<dim3(cdiv(N_, 128), cdiv(N_, 128)), 256, SYRK_SMEM>>>(pdh, pdl, out);
}